// round 6
// baseline (speedup 1.0000x reference)
#include <cuda_runtime.h>

#define N_NODES 50000
#define N_EDGES 800000
#define F 64
#define NCLS 10

#define SCAN_CHUNK 512
#define SCAN_BLOCKS ((N_NODES + SCAN_CHUNK - 1) / SCAN_CHUNK)   // 98
#define NODE_BLOCKS ((N_NODES + 255) / 256)                      // 196

// Scratch (__device__ globals; accessed directly as symbols — no
// cudaGetSymbolAddress, it breaks graph capture on this harness).
// Ping-pong buffers: a fused layer never reads and writes the same buffer.
__device__ float g_a[N_NODES * F];
__device__ float g_b[N_NODES * F];
__device__ int   g_deg[N_NODES];
__device__ int   g_offs[N_NODES + 1];
__device__ int   g_cursor[N_NODES];
__device__ int   g_csr[N_EDGES];
__device__ int   g_blocksum[SCAN_BLOCKS];
__device__ int   g_is64;

// ---------------------------------------------------------------------------
// f32x2 helpers (FFMA2 — only reachable via PTX)
// ---------------------------------------------------------------------------
__device__ __forceinline__ unsigned long long pack2(float lo, float hi) {
    unsigned long long r;
    asm("mov.b64 %0, {%1, %2};" : "=l"(r) : "f"(lo), "f"(hi));
    return r;
}
__device__ __forceinline__ float2 unpack2(unsigned long long v) {
    float2 f;
    asm("mov.b64 {%0, %1}, %2;" : "=f"(f.x), "=f"(f.y) : "l"(v));
    return f;
}
__device__ __forceinline__ void fma2(unsigned long long& d,
                                     unsigned long long a, unsigned long long b) {
    asm("fma.rn.f32x2 %0, %1, %2, %0;" : "+l"(d) : "l"(a), "l"(b));
}

// ---------------------------------------------------------------------------
// init: zero degree counters (blocks 0..NODE_BLOCKS-1) + dtype detect (last)
// ---------------------------------------------------------------------------
__global__ void init_kernel(const int* __restrict__ edges_raw) {
    if (blockIdx.x < NODE_BLOCKS) {
        int i = blockIdx.x * 256 + threadIdx.x;
        if (i < N_NODES) g_deg[i] = 0;
    } else {
        __shared__ int any_nonzero;
        if (threadIdx.x == 0) any_nonzero = 0;
        __syncthreads();
        int nz = 0;
        for (int i = threadIdx.x; i < 2048; i += 256)
            if (edges_raw[2 * i + 1] != 0) nz = 1;
        if (nz) any_nonzero = 1;
        __syncthreads();
        if (threadIdx.x == 0) g_is64 = (any_nonzero == 0) ? 1 : 0;
    }
}

__device__ __forceinline__ int load_id(const int* __restrict__ raw, int is64, int idx) {
    return is64 ? raw[2 * idx] : raw[idx];
}

__global__ void hist_kernel(const int* __restrict__ edges_raw) {
    int e = blockIdx.x * blockDim.x + threadIdx.x;
    if (e < N_EDGES) {
        int d = load_id(edges_raw, g_is64, N_EDGES + e);
        atomicAdd(&g_deg[d], 1);
    }
}

// Scan step 1: per-block exclusive scan via warp shuffles.
__global__ void scan_local_kernel() {
    __shared__ int warp_sums[SCAN_CHUNK / 32];
    int tid  = threadIdx.x;
    int gid  = blockIdx.x * SCAN_CHUNK + tid;
    int lane = tid & 31;
    int wid  = tid >> 5;

    int v = (gid < N_NODES) ? g_deg[gid] : 0;
    int x = v;
#pragma unroll
    for (int off = 1; off < 32; off <<= 1) {
        int y = __shfl_up_sync(0xFFFFFFFFu, x, off);
        if (lane >= off) x += y;
    }
    if (lane == 31) warp_sums[wid] = x;
    __syncthreads();
    if (wid == 0) {
        int s = (lane < SCAN_CHUNK / 32) ? warp_sums[lane] : 0;
#pragma unroll
        for (int off = 1; off < SCAN_CHUNK / 32; off <<= 1) {
            int y = __shfl_up_sync(0xFFFFFFFFu, s, off);
            if (lane >= off) s += y;
        }
        if (lane < SCAN_CHUNK / 32) warp_sums[lane] = s;
    }
    __syncthreads();
    int base = (wid > 0) ? warp_sums[wid - 1] : 0;
    int incl = base + x;
    if (gid < N_NODES) g_offs[gid] = incl - v;
    if (tid == SCAN_CHUNK - 1) g_blocksum[blockIdx.x] = incl;
}

// Scan step 2: scan the 98 block sums (single block, 128 thr).
__global__ void scan_spine_kernel() {
    __shared__ int ws[4];
    int tid  = threadIdx.x;
    int lane = tid & 31;
    int wid  = tid >> 5;
    int v = (tid < SCAN_BLOCKS) ? g_blocksum[tid] : 0;
    int x = v;
#pragma unroll
    for (int off = 1; off < 32; off <<= 1) {
        int y = __shfl_up_sync(0xFFFFFFFFu, x, off);
        if (lane >= off) x += y;
    }
    if (lane == 31) ws[wid] = x;
    __syncthreads();
    if (tid == 0) {
        int r = 0;
#pragma unroll
        for (int i = 0; i < 4; i++) { int t = ws[i]; ws[i] = r; r += t; }
    }
    __syncthreads();
    int excl = ws[wid] + x - v;
    if (tid < SCAN_BLOCKS) g_blocksum[tid] = excl;
    if (tid == SCAN_BLOCKS - 1) g_offs[N_NODES] = excl + v;
}

// Scan step 3: add spine; materialize offs + cursor.
__global__ void scan_add_kernel() {
    int gid = blockIdx.x * SCAN_CHUNK + threadIdx.x;
    if (gid < N_NODES) {
        int o = g_offs[gid] + g_blocksum[blockIdx.x];
        g_offs[gid]   = o;
        g_cursor[gid] = o;
    }
}

__global__ void csr_scatter_kernel(const int* __restrict__ edges_raw) {
    int e = blockIdx.x * blockDim.x + threadIdx.x;
    if (e >= N_EDGES) return;
    int is64 = g_is64;
    int s = load_id(edges_raw, is64, e);
    int d = load_id(edges_raw, is64, N_EDGES + e);
    int pos = atomicAdd(&g_cursor[d], 1);
    g_csr[pos] = s;
}

// ---------------------------------------------------------------------------
// Fused GIN layer: smem h = x + sum(neighbors), then
// out = relu( relu(h @ W1 + b1) @ W2 + b2 ), FFMA2 with K-pair packing.
// mode: 0 = feat->g_a, 1 = g_a->g_b, 2 = g_b->g_a.  (read buf != write buf)
// ---------------------------------------------------------------------------
#define HS_STRIDE 68   // float stride: multiple of 4 (16B STS.128 alignment)

__global__ __launch_bounds__(256) void gin_layer_kernel(
        const float* __restrict__ feat, int mode,
        const float* __restrict__ W1, const float* __restrict__ b1,
        const float* __restrict__ W2, const float* __restrict__ b2) {
    __shared__ __align__(16) float Hs[64 * HS_STRIDE];
    __shared__ __align__(16) float WsP[64 * 64];   // pair-interleaved: [m][2j+l] = W[2m+l][j]
    __shared__ float bias[64];

    const float* __restrict__ x   = (mode == 0) ? feat
                                   : (mode == 1) ? (const float*)g_a
                                                 : (const float*)g_b;
    float* __restrict__ outbuf     = (mode == 1) ? g_b : g_a;

    int tid  = threadIdx.x;
    int row0 = blockIdx.x * 64;

    // ---- Fill WsP(W1) + bias, and gather H tile ----
    for (int idx = tid; idx < 4096; idx += 256) {
        int k = idx >> 6, j = idx & 63;
        WsP[(k >> 1) * 128 + 2 * j + (k & 1)] = W1[idx];
    }
    if (tid < 64) bias[tid] = b1[tid];

    {
        int r = tid >> 2;            // 0..63 row in tile
        int q = tid & 3;             // k-quarter (16 floats)
        int node = row0 + r;
        float4 a0 = make_float4(0.f, 0.f, 0.f, 0.f), a1 = a0, a2 = a0, a3 = a0;
        if (node < N_NODES) {
            const float4* xr = (const float4*)(x + (size_t)node * F + q * 16);
            a0 = xr[0]; a1 = xr[1]; a2 = xr[2]; a3 = xr[3];
            int jb = g_offs[node], je = g_offs[node + 1];
            for (int j = jb; j < je; j++) {
                const float4* xs = (const float4*)(x + (size_t)g_csr[j] * F + q * 16);
                float4 v0 = xs[0], v1 = xs[1], v2 = xs[2], v3 = xs[3];
                a0.x += v0.x; a0.y += v0.y; a0.z += v0.z; a0.w += v0.w;
                a1.x += v1.x; a1.y += v1.y; a1.z += v1.z; a1.w += v1.w;
                a2.x += v2.x; a2.y += v2.y; a2.z += v2.z; a2.w += v2.w;
                a3.x += v3.x; a3.y += v3.y; a3.z += v3.z; a3.w += v3.w;
            }
        }
        float4* hrow = (float4*)&Hs[r * HS_STRIDE + q * 16];
        hrow[0] = a0; hrow[1] = a1; hrow[2] = a2; hrow[3] = a3;
    }
    __syncthreads();

    int tx = tid & 15;   // col group: cols tx + 16*jj
    int ty = tid >> 4;   // row group: rows ty*4 + i

    unsigned long long acc[4][4];
#pragma unroll
    for (int i = 0; i < 4; i++)
#pragma unroll
        for (int jj = 0; jj < 4; jj++)
            acc[i][jj] = pack2(bias[tx + 16 * jj], 0.f);

    // ---- Stage 1: T = relu(H @ W1 + b1) ----
#pragma unroll 4
    for (int m = 0; m < 32; m++) {
        unsigned long long ap[4], bp[4];
#pragma unroll
        for (int i = 0; i < 4; i++)
            ap[i] = *(const unsigned long long*)&Hs[(ty * 4 + i) * HS_STRIDE + 2 * m];
#pragma unroll
        for (int jj = 0; jj < 4; jj++)
            bp[jj] = *(const unsigned long long*)&WsP[m * 128 + 2 * (tx + 16 * jj)];
#pragma unroll
        for (int i = 0; i < 4; i++)
#pragma unroll
            for (int jj = 0; jj < 4; jj++)
                fma2(acc[i][jj], ap[i], bp[jj]);
    }
    __syncthreads();   // all Hs/WsP reads done

    // Write T = relu(lane0+lane1) into Hs; refill WsP(W2) + bias
#pragma unroll
    for (int i = 0; i < 4; i++)
#pragma unroll
        for (int jj = 0; jj < 4; jj++) {
            float2 f = unpack2(acc[i][jj]);
            Hs[(ty * 4 + i) * HS_STRIDE + tx + 16 * jj] = fmaxf(f.x + f.y, 0.f);
        }
    for (int idx = tid; idx < 4096; idx += 256) {
        int k = idx >> 6, j = idx & 63;
        WsP[(k >> 1) * 128 + 2 * j + (k & 1)] = W2[idx];
    }
    if (tid < 64) bias[tid] = b2[tid];
    __syncthreads();

#pragma unroll
    for (int i = 0; i < 4; i++)
#pragma unroll
        for (int jj = 0; jj < 4; jj++)
            acc[i][jj] = pack2(bias[tx + 16 * jj], 0.f);

    // ---- Stage 2: O = relu(T @ W2 + b2) ----
#pragma unroll 4
    for (int m = 0; m < 32; m++) {
        unsigned long long ap[4], bp[4];
#pragma unroll
        for (int i = 0; i < 4; i++)
            ap[i] = *(const unsigned long long*)&Hs[(ty * 4 + i) * HS_STRIDE + 2 * m];
#pragma unroll
        for (int jj = 0; jj < 4; jj++)
            bp[jj] = *(const unsigned long long*)&WsP[m * 128 + 2 * (tx + 16 * jj)];
#pragma unroll
        for (int i = 0; i < 4; i++)
#pragma unroll
            for (int jj = 0; jj < 4; jj++)
                fma2(acc[i][jj], ap[i], bp[jj]);
    }

#pragma unroll
    for (int i = 0; i < 4; i++) {
        int r = row0 + ty * 4 + i;
        if (r < N_NODES) {
#pragma unroll
            for (int jj = 0; jj < 4; jj++) {
                float2 f = unpack2(acc[i][jj]);
                outbuf[(size_t)r * F + tx + 16 * jj] = fmaxf(f.x + f.y, 0.f);
            }
        }
    }
}

// ---------------------------------------------------------------------------
// out = g_a @ W_lin + b_lin   (64 -> 10)
// ---------------------------------------------------------------------------
__global__ void lin_kernel(const float* __restrict__ W, const float* __restrict__ b,
                           float* __restrict__ out) {
    __shared__ float Xs[128][65];
    __shared__ float Ws[64 * NCLS];
    __shared__ float bs[NCLS];

    int tid = threadIdx.x;
    int row0 = blockIdx.x * 128;

    for (int i = tid; i < 128 * 16; i += 128) {
        int r = i >> 4;
        int c = (i & 15) << 2;
        float4 v = make_float4(0.f, 0.f, 0.f, 0.f);
        if (row0 + r < N_NODES) v = *(const float4*)(g_a + (size_t)(row0 + r) * F + c);
        Xs[r][c] = v.x; Xs[r][c + 1] = v.y; Xs[r][c + 2] = v.z; Xs[r][c + 3] = v.w;
    }
    for (int i = tid; i < 64 * NCLS; i += 128) Ws[i] = W[i];
    if (tid < NCLS) bs[tid] = b[tid];
    __syncthreads();

    int row = row0 + tid;
    float acc[NCLS];
#pragma unroll
    for (int c = 0; c < NCLS; c++) acc[c] = bs[c];
#pragma unroll 8
    for (int k = 0; k < 64; k++) {
        float xv = Xs[tid][k];
#pragma unroll
        for (int c = 0; c < NCLS; c++) acc[c] += xv * Ws[k * NCLS + c];
    }
    if (row < N_NODES) {
#pragma unroll
        for (int c = 0; c < NCLS; c++) out[(size_t)row * NCLS + c] = acc[c];
    }
}

// ---------------------------------------------------------------------------
// Launch: kernel launches ONLY.
// ---------------------------------------------------------------------------
extern "C" void kernel_launch(void* const* d_in, const int* in_sizes, int n_in,
                              void* d_out, int out_size) {
    const float* feat      = (const float*)d_in[0];
    const int*   edges_raw = (const int*)d_in[1];

    const float* W1[3] = { (const float*)d_in[2],  (const float*)d_in[6],  (const float*)d_in[10] };
    const float* b1[3] = { (const float*)d_in[3],  (const float*)d_in[7],  (const float*)d_in[11] };
    const float* W2[3] = { (const float*)d_in[4],  (const float*)d_in[8],  (const float*)d_in[12] };
    const float* b2[3] = { (const float*)d_in[5],  (const float*)d_in[9],  (const float*)d_in[13] };
    const float* Wl = (const float*)d_in[14];
    const float* bl = (const float*)d_in[15];
    float* out = (float*)d_out;

    dim3 edge_grid((N_EDGES + 255) / 256);
    dim3 layer_grid((N_NODES + 63) / 64);
    dim3 lin_grid((N_NODES + 127) / 128);

    init_kernel<<<NODE_BLOCKS + 1, 256>>>(edges_raw);
    hist_kernel<<<edge_grid, 256>>>(edges_raw);
    scan_local_kernel<<<SCAN_BLOCKS, SCAN_CHUNK>>>();
    scan_spine_kernel<<<1, 128>>>();
    scan_add_kernel<<<SCAN_BLOCKS, SCAN_CHUNK>>>();
    csr_scatter_kernel<<<edge_grid, 256>>>(edges_raw);

    // mode 0: feat -> g_a, mode 1: g_a -> g_b, mode 2: g_b -> g_a
    gin_layer_kernel<<<layer_grid, 256>>>(feat, 0, W1[0], b1[0], W2[0], b2[0]);
    gin_layer_kernel<<<layer_grid, 256>>>(feat, 1, W1[1], b1[1], W2[1], b2[1]);
    gin_layer_kernel<<<layer_grid, 256>>>(feat, 2, W1[2], b1[2], W2[2], b2[2]);
    lin_kernel<<<lin_grid, 128>>>(Wl, bl, out);
}

// round 7
// speedup vs baseline: 1.2385x; 1.2385x over previous
#include <cuda_runtime.h>

#define N_NODES 50000
#define N_EDGES 800000
#define F 64
#define NCLS 10

#define SCAN_CHUNK 512
#define SCAN_BLOCKS ((N_NODES + SCAN_CHUNK - 1) / SCAN_CHUNK)   // 98
#define NODE_BLOCKS ((N_NODES + 255) / 256)                      // 196

// Scratch (__device__ globals; accessed directly as symbols).
__device__ float g_h[N_NODES * F];
__device__ float g_x[N_NODES * F];
__device__ int   g_deg[N_NODES];
__device__ int   g_offs[N_NODES + 1];
__device__ int   g_cursor[N_NODES];
__device__ int   g_csr[N_EDGES];
__device__ int   g_blocksum[SCAN_BLOCKS];
__device__ int   g_is64;

// ---------------------------------------------------------------------------
// f32x2 helpers (FFMA2 — only reachable via PTX)
// ---------------------------------------------------------------------------
__device__ __forceinline__ unsigned long long pack2(float lo, float hi) {
    unsigned long long r;
    asm("mov.b64 %0, {%1, %2};" : "=l"(r) : "f"(lo), "f"(hi));
    return r;
}
__device__ __forceinline__ float2 unpack2(unsigned long long v) {
    float2 f;
    asm("mov.b64 {%0, %1}, %2;" : "=f"(f.x), "=f"(f.y) : "l"(v));
    return f;
}
__device__ __forceinline__ void fma2(unsigned long long& d,
                                     unsigned long long a, unsigned long long b) {
    asm("fma.rn.f32x2 %0, %1, %2, %0;" : "+l"(d) : "l"(a), "l"(b));
}

// ---------------------------------------------------------------------------
// init: zero degree counters + dtype detect (last block)
// ---------------------------------------------------------------------------
__global__ void init_kernel(const int* __restrict__ edges_raw) {
    if (blockIdx.x < NODE_BLOCKS) {
        int i = blockIdx.x * 256 + threadIdx.x;
        if (i < N_NODES) g_deg[i] = 0;
    } else {
        __shared__ int any_nonzero;
        if (threadIdx.x == 0) any_nonzero = 0;
        __syncthreads();
        int nz = 0;
        for (int i = threadIdx.x; i < 2048; i += 256)
            if (edges_raw[2 * i + 1] != 0) nz = 1;
        if (nz) any_nonzero = 1;
        __syncthreads();
        if (threadIdx.x == 0) g_is64 = (any_nonzero == 0) ? 1 : 0;
    }
}

__device__ __forceinline__ int load_id(const int* __restrict__ raw, int is64, int idx) {
    return is64 ? raw[2 * idx] : raw[idx];
}

__global__ void hist_kernel(const int* __restrict__ edges_raw) {
    int e = blockIdx.x * blockDim.x + threadIdx.x;
    if (e < N_EDGES) {
        int d = load_id(edges_raw, g_is64, N_EDGES + e);
        atomicAdd(&g_deg[d], 1);
    }
}

// Scan step 1: per-block exclusive scan via warp shuffles.
__global__ void scan_local_kernel() {
    __shared__ int warp_sums[SCAN_CHUNK / 32];
    int tid  = threadIdx.x;
    int gid  = blockIdx.x * SCAN_CHUNK + tid;
    int lane = tid & 31;
    int wid  = tid >> 5;

    int v = (gid < N_NODES) ? g_deg[gid] : 0;
    int x = v;
#pragma unroll
    for (int off = 1; off < 32; off <<= 1) {
        int y = __shfl_up_sync(0xFFFFFFFFu, x, off);
        if (lane >= off) x += y;
    }
    if (lane == 31) warp_sums[wid] = x;
    __syncthreads();
    if (wid == 0) {
        int s = (lane < SCAN_CHUNK / 32) ? warp_sums[lane] : 0;
#pragma unroll
        for (int off = 1; off < SCAN_CHUNK / 32; off <<= 1) {
            int y = __shfl_up_sync(0xFFFFFFFFu, s, off);
            if (lane >= off) s += y;
        }
        if (lane < SCAN_CHUNK / 32) warp_sums[lane] = s;
    }
    __syncthreads();
    int base = (wid > 0) ? warp_sums[wid - 1] : 0;
    int incl = base + x;
    if (gid < N_NODES) g_offs[gid] = incl - v;
    if (tid == SCAN_CHUNK - 1) g_blocksum[blockIdx.x] = incl;
}

// Scan step 2: scan the 98 block sums.
__global__ void scan_spine_kernel() {
    __shared__ int ws[4];
    int tid  = threadIdx.x;
    int lane = tid & 31;
    int wid  = tid >> 5;
    int v = (tid < SCAN_BLOCKS) ? g_blocksum[tid] : 0;
    int x = v;
#pragma unroll
    for (int off = 1; off < 32; off <<= 1) {
        int y = __shfl_up_sync(0xFFFFFFFFu, x, off);
        if (lane >= off) x += y;
    }
    if (lane == 31) ws[wid] = x;
    __syncthreads();
    if (tid == 0) {
        int r = 0;
#pragma unroll
        for (int i = 0; i < 4; i++) { int t = ws[i]; ws[i] = r; r += t; }
    }
    __syncthreads();
    int excl = ws[wid] + x - v;
    if (tid < SCAN_BLOCKS) g_blocksum[tid] = excl;
    if (tid == SCAN_BLOCKS - 1) g_offs[N_NODES] = excl + v;
}

// Scan step 3: add spine; materialize offs + cursor.
__global__ void scan_add_kernel() {
    int gid = blockIdx.x * SCAN_CHUNK + threadIdx.x;
    if (gid < N_NODES) {
        int o = g_offs[gid] + g_blocksum[blockIdx.x];
        g_offs[gid]   = o;
        g_cursor[gid] = o;
    }
}

__global__ void csr_scatter_kernel(const int* __restrict__ edges_raw) {
    int e = blockIdx.x * blockDim.x + threadIdx.x;
    if (e >= N_EDGES) return;
    int is64 = g_is64;
    int s = load_id(edges_raw, is64, e);
    int d = load_id(edges_raw, is64, N_EDGES + e);
    int pos = atomicAdd(&g_cursor[d], 1);
    g_csr[pos] = s;
}

// ---------------------------------------------------------------------------
// Aggregation (gather): g_h[n] = x[n] + sum_{s in N_in(n)} x[s]
// 16 threads per node, float4 per thread.   (unchanged from R4)
// ---------------------------------------------------------------------------
__global__ void agg_kernel(const float* __restrict__ feat, int first) {
    const float* __restrict__ x = first ? feat : (const float*)g_x;
    int tid  = threadIdx.x;
    int node = blockIdx.x * 16 + (tid >> 4);
    int t    = tid & 15;
    if (node >= N_NODES) return;

    float4 acc = *(const float4*)(x + (size_t)node * F + t * 4);
    int jb = g_offs[node];
    int je = g_offs[node + 1];
    for (int j = jb; j < je; j++) {
        int s = g_csr[j];
        float4 v = *(const float4*)(x + (size_t)s * F + t * 4);
        acc.x += v.x; acc.y += v.y; acc.z += v.z; acc.w += v.w;
    }
    *(float4*)(g_h + (size_t)node * F + t * 4) = acc;
}

// ---------------------------------------------------------------------------
// g_x = relu( relu(g_h @ W1 + b1) @ W2 + b2 )  — FFMA2 K-pair packing.
// 64-row tile per block, 256 threads as 16x16. acc lanes = even/odd-k partials.
// ---------------------------------------------------------------------------
#define HS_STRIDE 68   // float stride: multiple of 4 (16B alignment of rows)

__global__ __launch_bounds__(256) void mlp_kernel(
        const float* __restrict__ W1, const float* __restrict__ b1,
        const float* __restrict__ W2, const float* __restrict__ b2) {
    __shared__ __align__(16) float Hs[64 * HS_STRIDE];
    __shared__ __align__(16) float WsP[64 * 64];   // [m][2j+l] = W[2m+l][j]
    __shared__ float bias[64];

    int tid  = threadIdx.x;
    int row0 = blockIdx.x * 64;

    // Load H tile (coalesced float4), W1 pair-interleaved, b1
    for (int i = tid; i < 64 * 16; i += 256) {
        int r = i >> 4;
        int c = (i & 15) << 2;
        float4 v = make_float4(0.f, 0.f, 0.f, 0.f);
        if (row0 + r < N_NODES) v = *(const float4*)(g_h + (size_t)(row0 + r) * F + c);
        *(float4*)&Hs[r * HS_STRIDE + c] = v;
    }
    for (int idx = tid; idx < 4096; idx += 256) {
        int k = idx >> 6, j = idx & 63;
        WsP[(k >> 1) * 128 + 2 * j + (k & 1)] = W1[idx];
    }
    if (tid < 64) bias[tid] = b1[tid];
    __syncthreads();

    int tx = tid & 15;   // col group: cols tx + 16*jj
    int ty = tid >> 4;   // row group: rows ty*4 + i

    unsigned long long acc[4][4];
#pragma unroll
    for (int i = 0; i < 4; i++)
#pragma unroll
        for (int jj = 0; jj < 4; jj++)
            acc[i][jj] = pack2(bias[tx + 16 * jj], 0.f);

    // Stage 1: T = relu(H @ W1 + b1)
#pragma unroll 4
    for (int m = 0; m < 32; m++) {
        unsigned long long ap[4], bp[4];
#pragma unroll
        for (int i = 0; i < 4; i++)
            ap[i] = *(const unsigned long long*)&Hs[(ty * 4 + i) * HS_STRIDE + 2 * m];
#pragma unroll
        for (int jj = 0; jj < 4; jj++)
            bp[jj] = *(const unsigned long long*)&WsP[m * 128 + 2 * (tx + 16 * jj)];
#pragma unroll
        for (int i = 0; i < 4; i++)
#pragma unroll
            for (int jj = 0; jj < 4; jj++)
                fma2(acc[i][jj], ap[i], bp[jj]);
    }
    __syncthreads();

    // T = relu(lane0+lane1) into Hs; refill WsP(W2) + bias
#pragma unroll
    for (int i = 0; i < 4; i++)
#pragma unroll
        for (int jj = 0; jj < 4; jj++) {
            float2 f = unpack2(acc[i][jj]);
            Hs[(ty * 4 + i) * HS_STRIDE + tx + 16 * jj] = fmaxf(f.x + f.y, 0.f);
        }
    for (int idx = tid; idx < 4096; idx += 256) {
        int k = idx >> 6, j = idx & 63;
        WsP[(k >> 1) * 128 + 2 * j + (k & 1)] = W2[idx];
    }
    if (tid < 64) bias[tid] = b2[tid];
    __syncthreads();

#pragma unroll
    for (int i = 0; i < 4; i++)
#pragma unroll
        for (int jj = 0; jj < 4; jj++)
            acc[i][jj] = pack2(bias[tx + 16 * jj], 0.f);

    // Stage 2: O = relu(T @ W2 + b2)
#pragma unroll 4
    for (int m = 0; m < 32; m++) {
        unsigned long long ap[4], bp[4];
#pragma unroll
        for (int i = 0; i < 4; i++)
            ap[i] = *(const unsigned long long*)&Hs[(ty * 4 + i) * HS_STRIDE + 2 * m];
#pragma unroll
        for (int jj = 0; jj < 4; jj++)
            bp[jj] = *(const unsigned long long*)&WsP[m * 128 + 2 * (tx + 16 * jj)];
#pragma unroll
        for (int i = 0; i < 4; i++)
#pragma unroll
            for (int jj = 0; jj < 4; jj++)
                fma2(acc[i][jj], ap[i], bp[jj]);
    }

#pragma unroll
    for (int i = 0; i < 4; i++) {
        int r = row0 + ty * 4 + i;
        if (r < N_NODES) {
#pragma unroll
            for (int jj = 0; jj < 4; jj++) {
                float2 f = unpack2(acc[i][jj]);
                g_x[(size_t)r * F + tx + 16 * jj] = fmaxf(f.x + f.y, 0.f);
            }
        }
    }
}

// ---------------------------------------------------------------------------
// out = g_x @ W_lin + b_lin   (64 -> 10)
// ---------------------------------------------------------------------------
__global__ void lin_kernel(const float* __restrict__ W, const float* __restrict__ b,
                           float* __restrict__ out) {
    __shared__ float Xs[128][65];
    __shared__ float Ws[64 * NCLS];
    __shared__ float bs[NCLS];

    int tid = threadIdx.x;
    int row0 = blockIdx.x * 128;

    for (int i = tid; i < 128 * 16; i += 128) {
        int r = i >> 4;
        int c = (i & 15) << 2;
        float4 v = make_float4(0.f, 0.f, 0.f, 0.f);
        if (row0 + r < N_NODES) v = *(const float4*)(g_x + (size_t)(row0 + r) * F + c);
        Xs[r][c] = v.x; Xs[r][c + 1] = v.y; Xs[r][c + 2] = v.z; Xs[r][c + 3] = v.w;
    }
    for (int i = tid; i < 64 * NCLS; i += 128) Ws[i] = W[i];
    if (tid < NCLS) bs[tid] = b[tid];
    __syncthreads();

    int row = row0 + tid;
    float acc[NCLS];
#pragma unroll
    for (int c = 0; c < NCLS; c++) acc[c] = bs[c];
#pragma unroll 8
    for (int k = 0; k < 64; k++) {
        float xv = Xs[tid][k];
#pragma unroll
        for (int c = 0; c < NCLS; c++) acc[c] += xv * Ws[k * NCLS + c];
    }
    if (row < N_NODES) {
#pragma unroll
        for (int c = 0; c < NCLS; c++) out[(size_t)row * NCLS + c] = acc[c];
    }
}

// ---------------------------------------------------------------------------
// Launch: kernel launches ONLY.
// ---------------------------------------------------------------------------
extern "C" void kernel_launch(void* const* d_in, const int* in_sizes, int n_in,
                              void* d_out, int out_size) {
    const float* feat      = (const float*)d_in[0];
    const int*   edges_raw = (const int*)d_in[1];

    const float* W1[3] = { (const float*)d_in[2],  (const float*)d_in[6],  (const float*)d_in[10] };
    const float* b1[3] = { (const float*)d_in[3],  (const float*)d_in[7],  (const float*)d_in[11] };
    const float* W2[3] = { (const float*)d_in[4],  (const float*)d_in[8],  (const float*)d_in[12] };
    const float* b2[3] = { (const float*)d_in[5],  (const float*)d_in[9],  (const float*)d_in[13] };
    const float* Wl = (const float*)d_in[14];
    const float* bl = (const float*)d_in[15];
    float* out = (float*)d_out;

    dim3 edge_grid((N_EDGES + 255) / 256);
    dim3 agg_grid((N_NODES + 15) / 16);
    dim3 mlp_grid((N_NODES + 63) / 64);
    dim3 lin_grid((N_NODES + 127) / 128);

    init_kernel<<<NODE_BLOCKS + 1, 256>>>(edges_raw);
    hist_kernel<<<edge_grid, 256>>>(edges_raw);
    scan_local_kernel<<<SCAN_BLOCKS, SCAN_CHUNK>>>();
    scan_spine_kernel<<<1, 128>>>();
    scan_add_kernel<<<SCAN_BLOCKS, SCAN_CHUNK>>>();
    csr_scatter_kernel<<<edge_grid, 256>>>(edges_raw);

    for (int l = 0; l < 3; l++) {
        agg_kernel<<<agg_grid, 256>>>(feat, l == 0 ? 1 : 0);
        mlp_kernel<<<mlp_grid, 256>>>(W1[l], b1[l], W2[l], b2[l]);
    }
    lin_kernel<<<lin_grid, 128>>>(Wl, bl, out);
}

// round 8
// speedup vs baseline: 1.3662x; 1.1031x over previous
#include <cuda_runtime.h>

#define N_NODES 50000
#define N_EDGES 800000
#define F 64
#define NCLS 10

#define SCAN_CHUNK 512
#define SCAN_BLOCKS ((N_NODES + SCAN_CHUNK - 1) / SCAN_CHUNK)   // 98
#define NODE_BLOCKS ((N_NODES + 255) / 256)                      // 196

// Scratch (__device__ globals; accessed directly as symbols).
__device__ float g_h[N_NODES * F];
__device__ float g_x[N_NODES * F];
__device__ int   g_deg[N_NODES];
__device__ int   g_offs[N_NODES + 1];
__device__ int   g_cursor[N_NODES];
__device__ int   g_csr[N_EDGES];
__device__ int   g_blocksum[SCAN_BLOCKS];
__device__ int   g_is64;

// ---------------------------------------------------------------------------
// init: zero degree counters + dtype detect (last block)
// ---------------------------------------------------------------------------
__global__ void init_kernel(const int* __restrict__ edges_raw) {
    if (blockIdx.x < NODE_BLOCKS) {
        int i = blockIdx.x * 256 + threadIdx.x;
        if (i < N_NODES) g_deg[i] = 0;
    } else {
        __shared__ int any_nonzero;
        if (threadIdx.x == 0) any_nonzero = 0;
        __syncthreads();
        int nz = 0;
        for (int i = threadIdx.x; i < 2048; i += 256)
            if (edges_raw[2 * i + 1] != 0) nz = 1;
        if (nz) any_nonzero = 1;
        __syncthreads();
        if (threadIdx.x == 0) g_is64 = (any_nonzero == 0) ? 1 : 0;
    }
}

__device__ __forceinline__ int load_id(const int* __restrict__ raw, int is64, int idx) {
    return is64 ? raw[2 * idx] : raw[idx];
}

__global__ void hist_kernel(const int* __restrict__ edges_raw) {
    int e = blockIdx.x * blockDim.x + threadIdx.x;
    if (e < N_EDGES) {
        int d = load_id(edges_raw, g_is64, N_EDGES + e);
        atomicAdd(&g_deg[d], 1);
    }
}

// Scan step 1: per-block exclusive scan via warp shuffles.
__global__ void scan_local_kernel() {
    __shared__ int warp_sums[SCAN_CHUNK / 32];
    int tid  = threadIdx.x;
    int gid  = blockIdx.x * SCAN_CHUNK + tid;
    int lane = tid & 31;
    int wid  = tid >> 5;

    int v = (gid < N_NODES) ? g_deg[gid] : 0;
    int x = v;
#pragma unroll
    for (int off = 1; off < 32; off <<= 1) {
        int y = __shfl_up_sync(0xFFFFFFFFu, x, off);
        if (lane >= off) x += y;
    }
    if (lane == 31) warp_sums[wid] = x;
    __syncthreads();
    if (wid == 0) {
        int s = (lane < SCAN_CHUNK / 32) ? warp_sums[lane] : 0;
#pragma unroll
        for (int off = 1; off < SCAN_CHUNK / 32; off <<= 1) {
            int y = __shfl_up_sync(0xFFFFFFFFu, s, off);
            if (lane >= off) s += y;
        }
        if (lane < SCAN_CHUNK / 32) warp_sums[lane] = s;
    }
    __syncthreads();
    int base = (wid > 0) ? warp_sums[wid - 1] : 0;
    int incl = base + x;
    if (gid < N_NODES) g_offs[gid] = incl - v;
    if (tid == SCAN_CHUNK - 1) g_blocksum[blockIdx.x] = incl;
}

// Scan step 2: scan the 98 block sums.
__global__ void scan_spine_kernel() {
    __shared__ int ws[4];
    int tid  = threadIdx.x;
    int lane = tid & 31;
    int wid  = tid >> 5;
    int v = (tid < SCAN_BLOCKS) ? g_blocksum[tid] : 0;
    int x = v;
#pragma unroll
    for (int off = 1; off < 32; off <<= 1) {
        int y = __shfl_up_sync(0xFFFFFFFFu, x, off);
        if (lane >= off) x += y;
    }
    if (lane == 31) ws[wid] = x;
    __syncthreads();
    if (tid == 0) {
        int r = 0;
#pragma unroll
        for (int i = 0; i < 4; i++) { int t = ws[i]; ws[i] = r; r += t; }
    }
    __syncthreads();
    int excl = ws[wid] + x - v;
    if (tid < SCAN_BLOCKS) g_blocksum[tid] = excl;
    if (tid == SCAN_BLOCKS - 1) g_offs[N_NODES] = excl + v;
}

// Scan step 3: add spine; materialize offs + cursor.
__global__ void scan_add_kernel() {
    int gid = blockIdx.x * SCAN_CHUNK + threadIdx.x;
    if (gid < N_NODES) {
        int o = g_offs[gid] + g_blocksum[blockIdx.x];
        g_offs[gid]   = o;
        g_cursor[gid] = o;
    }
}

__global__ void csr_scatter_kernel(const int* __restrict__ edges_raw) {
    int e = blockIdx.x * blockDim.x + threadIdx.x;
    if (e >= N_EDGES) return;
    int is64 = g_is64;
    int s = load_id(edges_raw, is64, e);
    int d = load_id(edges_raw, is64, N_EDGES + e);
    int pos = atomicAdd(&g_cursor[d], 1);
    g_csr[pos] = s;
}

// ---------------------------------------------------------------------------
// Aggregation (gather): g_h[n] = x[n] + sum_{s in N_in(n)} x[s]
// 16 threads per node, float4 per thread. Neighbor loop unrolled x4 for MLP.
// ---------------------------------------------------------------------------
__global__ void agg_kernel(const float* __restrict__ feat, int first) {
    const float* __restrict__ x = first ? feat : (const float*)g_x;
    int tid  = threadIdx.x;
    int node = blockIdx.x * 16 + (tid >> 4);
    int t    = tid & 15;
    if (node >= N_NODES) return;

    float4 acc = *(const float4*)(x + (size_t)node * F + t * 4);
    int jb = g_offs[node];
    int je = g_offs[node + 1];
    int j  = jb;
    for (; j + 3 < je; j += 4) {
        int s0 = g_csr[j], s1 = g_csr[j + 1], s2 = g_csr[j + 2], s3 = g_csr[j + 3];
        float4 v0 = *(const float4*)(x + (size_t)s0 * F + t * 4);
        float4 v1 = *(const float4*)(x + (size_t)s1 * F + t * 4);
        float4 v2 = *(const float4*)(x + (size_t)s2 * F + t * 4);
        float4 v3 = *(const float4*)(x + (size_t)s3 * F + t * 4);
        acc.x += v0.x; acc.y += v0.y; acc.z += v0.z; acc.w += v0.w;
        acc.x += v1.x; acc.y += v1.y; acc.z += v1.z; acc.w += v1.w;
        acc.x += v2.x; acc.y += v2.y; acc.z += v2.z; acc.w += v2.w;
        acc.x += v3.x; acc.y += v3.y; acc.z += v3.z; acc.w += v3.w;
    }
    for (; j < je; j++) {
        int s = g_csr[j];
        float4 v = *(const float4*)(x + (size_t)s * F + t * 4);
        acc.x += v.x; acc.y += v.y; acc.z += v.z; acc.w += v.w;
    }
    *(float4*)(g_h + (size_t)node * F + t * 4) = acc;
}

// ---------------------------------------------------------------------------
// g_x = relu( relu(g_h @ W1 + b1) @ W2 + b2 )
// 128-row tile per block, 512 threads as 16x32, 4x4 register microtile.
// Bias kept in registers (smem = Hs 32KB + Ws 16KB = 48KB exactly).
// ---------------------------------------------------------------------------
__global__ __launch_bounds__(512) void mlp_kernel(
        const float* __restrict__ W1, const float* __restrict__ b1,
        const float* __restrict__ W2, const float* __restrict__ b2) {
    __shared__ float Hs[128][64];   // a-reads are broadcast -> no padding needed
    __shared__ float Ws[64][64];

    int tid = threadIdx.x;
    int tx = tid & 15;          // col group (4 cols)
    int ty = tid >> 4;          // row group (4 rows), 0..31
    int row0 = blockIdx.x * 128;

    // Load H tile (128x64) coalesced float4
    for (int i = tid; i < 128 * 16; i += 512) {
        int r = i >> 4;
        int c = (i & 15) << 2;
        float4 v = make_float4(0.f, 0.f, 0.f, 0.f);
        if (row0 + r < N_NODES) v = *(const float4*)(g_h + (size_t)(row0 + r) * F + c);
        *(float4*)&Hs[r][c] = v;
    }
    for (int i = tid; i < 1024; i += 512)
        ((float4*)&Ws[0][0])[i] = ((const float4*)W1)[i];
    float4 bias = *(const float4*)&b1[tx * 4];
    __syncthreads();

    float acc[4][4];
#pragma unroll
    for (int i = 0; i < 4; i++) {
        acc[i][0] = bias.x; acc[i][1] = bias.y; acc[i][2] = bias.z; acc[i][3] = bias.w;
    }

    // Stage 1: T = relu(H @ W1 + b1)
#pragma unroll 8
    for (int k = 0; k < 64; k++) {
        float a0 = Hs[ty * 4 + 0][k];
        float a1 = Hs[ty * 4 + 1][k];
        float a2 = Hs[ty * 4 + 2][k];
        float a3 = Hs[ty * 4 + 3][k];
        float4 b = *(float4*)&Ws[k][tx * 4];
        acc[0][0] += a0 * b.x; acc[0][1] += a0 * b.y; acc[0][2] += a0 * b.z; acc[0][3] += a0 * b.w;
        acc[1][0] += a1 * b.x; acc[1][1] += a1 * b.y; acc[1][2] += a1 * b.z; acc[1][3] += a1 * b.w;
        acc[2][0] += a2 * b.x; acc[2][1] += a2 * b.y; acc[2][2] += a2 * b.z; acc[2][3] += a2 * b.w;
        acc[3][0] += a3 * b.x; acc[3][1] += a3 * b.y; acc[3][2] += a3 * b.z; acc[3][3] += a3 * b.w;
    }
    __syncthreads();   // all Hs/Ws reads done

    // Write T = relu(acc) back into Hs; load W2; bias2 in regs
#pragma unroll
    for (int i = 0; i < 4; i++)
#pragma unroll
        for (int j = 0; j < 4; j++)
            Hs[ty * 4 + i][tx * 4 + j] = fmaxf(acc[i][j], 0.f);
    for (int i = tid; i < 1024; i += 512)
        ((float4*)&Ws[0][0])[i] = ((const float4*)W2)[i];
    bias = *(const float4*)&b2[tx * 4];
    __syncthreads();

#pragma unroll
    for (int i = 0; i < 4; i++) {
        acc[i][0] = bias.x; acc[i][1] = bias.y; acc[i][2] = bias.z; acc[i][3] = bias.w;
    }

    // Stage 2: O = relu(T @ W2 + b2)
#pragma unroll 8
    for (int k = 0; k < 64; k++) {
        float a0 = Hs[ty * 4 + 0][k];
        float a1 = Hs[ty * 4 + 1][k];
        float a2 = Hs[ty * 4 + 2][k];
        float a3 = Hs[ty * 4 + 3][k];
        float4 b = *(float4*)&Ws[k][tx * 4];
        acc[0][0] += a0 * b.x; acc[0][1] += a0 * b.y; acc[0][2] += a0 * b.z; acc[0][3] += a0 * b.w;
        acc[1][0] += a1 * b.x; acc[1][1] += a1 * b.y; acc[1][2] += a1 * b.z; acc[1][3] += a1 * b.w;
        acc[2][0] += a2 * b.x; acc[2][1] += a2 * b.y; acc[2][2] += a2 * b.z; acc[2][3] += a2 * b.w;
        acc[3][0] += a3 * b.x; acc[3][1] += a3 * b.y; acc[3][2] += a3 * b.z; acc[3][3] += a3 * b.w;
    }

#pragma unroll
    for (int i = 0; i < 4; i++) {
        int r = row0 + ty * 4 + i;
        if (r < N_NODES) {
            float4 o;
            o.x = fmaxf(acc[i][0], 0.f); o.y = fmaxf(acc[i][1], 0.f);
            o.z = fmaxf(acc[i][2], 0.f); o.w = fmaxf(acc[i][3], 0.f);
            *(float4*)(g_x + (size_t)r * F + tx * 4) = o;
        }
    }
}

// ---------------------------------------------------------------------------
// out = g_x @ W_lin + b_lin   (64 -> 10)
// ---------------------------------------------------------------------------
__global__ void lin_kernel(const float* __restrict__ W, const float* __restrict__ b,
                           float* __restrict__ out) {
    __shared__ float Xs[128][65];
    __shared__ float Ws[64 * NCLS];
    __shared__ float bs[NCLS];

    int tid = threadIdx.x;
    int row0 = blockIdx.x * 128;

    for (int i = tid; i < 128 * 16; i += 128) {
        int r = i >> 4;
        int c = (i & 15) << 2;
        float4 v = make_float4(0.f, 0.f, 0.f, 0.f);
        if (row0 + r < N_NODES) v = *(const float4*)(g_x + (size_t)(row0 + r) * F + c);
        Xs[r][c] = v.x; Xs[r][c + 1] = v.y; Xs[r][c + 2] = v.z; Xs[r][c + 3] = v.w;
    }
    for (int i = tid; i < 64 * NCLS; i += 128) Ws[i] = W[i];
    if (tid < NCLS) bs[tid] = b[tid];
    __syncthreads();

    int row = row0 + tid;
    float acc[NCLS];
#pragma unroll
    for (int c = 0; c < NCLS; c++) acc[c] = bs[c];
#pragma unroll 8
    for (int k = 0; k < 64; k++) {
        float xv = Xs[tid][k];
#pragma unroll
        for (int c = 0; c < NCLS; c++) acc[c] += xv * Ws[k * NCLS + c];
    }
    if (row < N_NODES) {
#pragma unroll
        for (int c = 0; c < NCLS; c++) out[(size_t)row * NCLS + c] = acc[c];
    }
}

// ---------------------------------------------------------------------------
// Launch: kernel launches ONLY.
// ---------------------------------------------------------------------------
extern "C" void kernel_launch(void* const* d_in, const int* in_sizes, int n_in,
                              void* d_out, int out_size) {
    const float* feat      = (const float*)d_in[0];
    const int*   edges_raw = (const int*)d_in[1];

    const float* W1[3] = { (const float*)d_in[2],  (const float*)d_in[6],  (const float*)d_in[10] };
    const float* b1[3] = { (const float*)d_in[3],  (const float*)d_in[7],  (const float*)d_in[11] };
    const float* W2[3] = { (const float*)d_in[4],  (const float*)d_in[8],  (const float*)d_in[12] };
    const float* b2[3] = { (const float*)d_in[5],  (const float*)d_in[9],  (const float*)d_in[13] };
    const float* Wl = (const float*)d_in[14];
    const float* bl = (const float*)d_in[15];
    float* out = (float*)d_out;

    dim3 edge_grid((N_EDGES + 255) / 256);
    dim3 agg_grid((N_NODES + 15) / 16);
    dim3 mlp_grid((N_NODES + 127) / 128);
    dim3 lin_grid((N_NODES + 127) / 128);

    init_kernel<<<NODE_BLOCKS + 1, 256>>>(edges_raw);
    hist_kernel<<<edge_grid, 256>>>(edges_raw);
    scan_local_kernel<<<SCAN_BLOCKS, SCAN_CHUNK>>>();
    scan_spine_kernel<<<1, 128>>>();
    scan_add_kernel<<<SCAN_BLOCKS, SCAN_CHUNK>>>();
    csr_scatter_kernel<<<edge_grid, 256>>>(edges_raw);

    for (int l = 0; l < 3; l++) {
        agg_kernel<<<agg_grid, 256>>>(feat, l == 0 ? 1 : 0);
        mlp_kernel<<<mlp_grid, 512>>>(W1[l], b1[l], W2[l], b2[l]);
    }
    lin_kernel<<<lin_grid, 128>>>(Wl, bl, out);
}